// round 1
// baseline (speedup 1.0000x reference)
#include <cuda_runtime.h>
#include <cuda_bf16.h>
#include <math.h>

// LSTM: T=512, B=64, I=512, H=512.
// gates[b, 0:4H] = concat(x_t, h)[b, 0:1024] @ W[1024, 4H] + bias
// f = sig(g[:, :H]); i = sig(g[:, H:2H]); cand = tanh(g[:, 2H:3H]); o = sig(g[:, 3H:])
// c = f*c + i*cand; h = o*tanh(c)
//
// Persistent cooperative kernel, 128 CTAs (co-resident on 148/152 SMs).
// CTA id = cg*4 + kg:  cg in [0,32) owns 64 gate columns, kg in [0,4) owns 256 of K=1024.
// W slice (256x64 fp32 = 64KB) cached in SMEM for the whole kernel.
// Per step: stage input slice -> SMEM, 64x64x256 fp32 GEMM (4x4 reg tiles),
// write partial to global scratch, grid barrier, per-(b,j) owner threads reduce
// 4 partials + bias, apply gates (c kept in registers), write h, barrier.

#define T_STEPS 512
#define B_SZ    64
#define I_SZ    512
#define H_SZ    512
#define G4      2048          // 4*H
#define KTOT    1024          // I + H
#define NCTA    128
#define NTHR    256
#define KG_SZ   256           // K per k-group
#define CG_COLS 64            // gate cols per col-group

// scratch (static device allocations are the sanctioned scratch mechanism)
__device__ float    g_hbuf[B_SZ * H_SZ];              // h state, [b][j]
__device__ float    g_part[4 * G4 * B_SZ];            // partials [kg][col][b]
__device__ unsigned g_bar;                            // monotonic barrier counter

__device__ __forceinline__ void grid_barrier(unsigned target) {
    __syncthreads();
    if (threadIdx.x == 0) {
        unsigned* bar = &g_bar;
        asm volatile("red.release.gpu.add.u32 [%0], 1;" :: "l"(bar) : "memory");
        unsigned v;
        do {
            asm volatile("ld.acquire.gpu.u32 %0, [%1];" : "=r"(v) : "l"(bar) : "memory");
        } while (v < target);
    }
    __syncthreads();
}

__device__ __forceinline__ float sigmoidf_fast(float x) {
    return 1.0f / (1.0f + __expf(-x));
}

extern "C" __global__ void __launch_bounds__(NTHR, 1)
lstm_persistent_kernel(const float* __restrict__ x,
                       const float* __restrict__ hidden0,
                       const float* __restrict__ cell0,
                       const float* __restrict__ W,
                       const float* __restrict__ bias,
                       float* __restrict__ out)
{
    extern __shared__ float smem[];
    float* Ws    = smem;                 // [256][64]   = 16384 floats
    float* In    = smem + 16384;         // [64][256]   = 16384 floats
    float* sbias = smem + 32768;         // [16]

    const int tid = threadIdx.x;
    const int bid = blockIdx.x;
    const int cg  = bid >> 2;            // 0..31
    const int kg  = bid & 3;             // 0..3

    // GEMM thread tiling: 16x16 threads, 4x4 register tile each
    const int tx = tid & 15;             // col tile
    const int ty = tid >> 4;             // batch tile

    // elementwise ownership: thread -> (batch eb, local h-index ejj)
    const int eb  = tid >> 2;            // 0..63
    const int ejj = tid & 3;             // 0..3
    const int ej  = bid * 4 + ejj;       // global h index 0..511

    // ---- init ----
    // cache W slice in SMEM (rows kg*256.., cols cg*64..); coalesced along cols
    {
        const float* wsrc = W + (size_t)(kg * KG_SZ) * G4 + cg * CG_COLS;
        #pragma unroll 4
        for (int r = tid; r < KG_SZ * CG_COLS; r += NTHR) {
            int kk = r >> 6;
            int cc = r & 63;
            Ws[kk * CG_COLS + cc] = wsrc[(size_t)kk * G4 + cc];
        }
    }
    // bias for this CTA's 16 gate columns: index tid = gate*4 + jj
    if (tid < 16) {
        int gate = tid >> 2;
        int jj   = tid & 3;
        sbias[tid] = bias[gate * H_SZ + bid * 4 + jj];
    }
    // state init
    float c_state = cell0[eb * H_SZ + ej];
    g_hbuf[eb * H_SZ + ej] = hidden0[eb * H_SZ + ej];
    float h_last = 0.0f;

    unsigned bar_n = 1;
    grid_barrier(NCTA * bar_n); bar_n++;

    // ---- time loop ----
    for (int t = 0; t < T_STEPS; t++) {
        // stage input slice In[b][kk]: concat(x_t, h)[b][kg*256 + kk]
        {
            const float* src = (kg < 2)
                ? (x + (size_t)t * B_SZ * I_SZ + kg * KG_SZ)
                : (g_hbuf + (kg - 2) * KG_SZ);
            // 4096 float4 chunks; lanes walk kq first -> coalesced gmem, clean sts
            #pragma unroll 4
            for (int r = tid; r < 64 * 64; r += NTHR) {
                int b  = r >> 6;
                int kq = r & 63;
                float4 v = *reinterpret_cast<const float4*>(src + b * 512 + kq * 4);
                *reinterpret_cast<float4*>(&In[b * KG_SZ + kq * 4]) = v;
            }
        }
        __syncthreads();

        // 64x64x256 fp32 GEMM, 4x4 register tile
        float acc00=0,acc01=0,acc02=0,acc03=0;
        float acc10=0,acc11=0,acc12=0,acc13=0;
        float acc20=0,acc21=0,acc22=0,acc23=0;
        float acc30=0,acc31=0,acc32=0,acc33=0;
        {
            const float* in0 = &In[(ty * 4 + 0) * KG_SZ];
            const float* in1 = &In[(ty * 4 + 1) * KG_SZ];
            const float* in2 = &In[(ty * 4 + 2) * KG_SZ];
            const float* in3 = &In[(ty * 4 + 3) * KG_SZ];
            const float* wcol = &Ws[tx * 4];
            #pragma unroll 8
            for (int kk = 0; kk < KG_SZ; kk++) {
                float4 bf = *reinterpret_cast<const float4*>(wcol + kk * CG_COLS);
                float a0 = in0[kk];
                float a1 = in1[kk];
                float a2 = in2[kk];
                float a3 = in3[kk];
                acc00 = fmaf(a0, bf.x, acc00); acc01 = fmaf(a0, bf.y, acc01);
                acc02 = fmaf(a0, bf.z, acc02); acc03 = fmaf(a0, bf.w, acc03);
                acc10 = fmaf(a1, bf.x, acc10); acc11 = fmaf(a1, bf.y, acc11);
                acc12 = fmaf(a1, bf.z, acc12); acc13 = fmaf(a1, bf.w, acc13);
                acc20 = fmaf(a2, bf.x, acc20); acc21 = fmaf(a2, bf.y, acc21);
                acc22 = fmaf(a2, bf.z, acc22); acc23 = fmaf(a2, bf.w, acc23);
                acc30 = fmaf(a3, bf.x, acc30); acc31 = fmaf(a3, bf.y, acc31);
                acc32 = fmaf(a3, bf.z, acc32); acc33 = fmaf(a3, bf.w, acc33);
            }
        }
        // write partials: g_part[kg][col][b]
        {
            float accs[4][4] = {{acc00,acc01,acc02,acc03},
                                {acc10,acc11,acc12,acc13},
                                {acc20,acc21,acc22,acc23},
                                {acc30,acc31,acc32,acc33}};
            int colbase = cg * CG_COLS + tx * 4;
            int bbase   = ty * 4;
            #pragma unroll
            for (int i = 0; i < 4; i++) {
                #pragma unroll
                for (int j = 0; j < 4; j++) {
                    g_part[((size_t)kg * G4 + colbase + j) * B_SZ + bbase + i] = accs[i][j];
                }
            }
        }

        grid_barrier(NCTA * bar_n); bar_n++;

        // elementwise: reduce 4 partials + bias, apply LSTM cell
        {
            float g0 = sbias[0 * 4 + ejj];
            float g1 = sbias[1 * 4 + ejj];
            float g2 = sbias[2 * 4 + ejj];
            float g3 = sbias[3 * 4 + ejj];
            #pragma unroll
            for (int kk = 0; kk < 4; kk++) {
                g0 += g_part[((size_t)kk * G4 + 0 * H_SZ + ej) * B_SZ + eb];
                g1 += g_part[((size_t)kk * G4 + 1 * H_SZ + ej) * B_SZ + eb];
                g2 += g_part[((size_t)kk * G4 + 2 * H_SZ + ej) * B_SZ + eb];
                g3 += g_part[((size_t)kk * G4 + 3 * H_SZ + ej) * B_SZ + eb];
            }
            float f  = sigmoidf_fast(g0);
            float ii = sigmoidf_fast(g1);
            float cd = tanhf(g2);
            float o  = sigmoidf_fast(g3);
            c_state = f * c_state + ii * cd;
            float h = o * tanhf(c_state);
            h_last = h;
            out[(size_t)t * (B_SZ * H_SZ) + eb * H_SZ + ej] = h;
            g_hbuf[eb * H_SZ + ej] = h;
        }

        grid_barrier(NCTA * bar_n); bar_n++;
    }

    // final states: out layout = output[T,B,H] ++ h_T[1,B,H] ++ c_T[1,B,H]
    {
        size_t base = (size_t)T_STEPS * B_SZ * H_SZ;
        out[base + eb * H_SZ + ej] = h_last;
        out[base + B_SZ * H_SZ + eb * H_SZ + ej] = c_state;
    }
}

extern "C" void kernel_launch(void* const* d_in, const int* in_sizes, int n_in,
                              void* d_out, int out_size)
{
    (void)in_sizes; (void)n_in; (void)out_size;
    const float* x       = (const float*)d_in[0];
    const float* hidden0 = (const float*)d_in[1];
    const float* cell0   = (const float*)d_in[2];
    const float* W       = (const float*)d_in[3];
    const float* bias    = (const float*)d_in[4];
    float* out = (float*)d_out;

    // reset barrier counter (graph-capturable async memset on default stream)
    void* bar_addr = nullptr;
    cudaGetSymbolAddress(&bar_addr, g_bar);
    cudaMemsetAsync(bar_addr, 0, sizeof(unsigned));

    const int smem_bytes = (16384 + 16384 + 16) * sizeof(float);  // 131136
    cudaFuncSetAttribute(lstm_persistent_kernel,
                         cudaFuncAttributeMaxDynamicSharedMemorySize, smem_bytes);

    lstm_persistent_kernel<<<NCTA, NTHR, smem_bytes>>>(x, hidden0, cell0, W, bias, out);
}

// round 3
// speedup vs baseline: 2.0348x; 2.0348x over previous
#include <cuda_runtime.h>
#include <cuda_bf16.h>
#include <math.h>
#include <stdint.h>

// LSTM T=512, B=64, I=H=512 on GB300 (sm_103a, compiled via compute_103 -> HMMA path).
// Persistent 128-CTA cooperative kernel, 2 grid barriers per step.
// CTA = cg*4+kg: cg in [0,32) owns 64 gate cols, kg in [0,4) owns 256 of K=1024.
// Per step: gates_partial = A(64x256) @ W(256x64) via mma.sync m16n8k16 bf16,
// 3-pass split: A_hi*W_hi + A_hi*W_lo + A_lo*W_hi (fp32 accum).
// W hi/lo cached in SMEM for all 512 steps. x pre-split to bf16 hi/lo once.

#define T_STEPS 512
#define B_SZ    64
#define H_SZ    512
#define I_SZ    512
#define G4      2048
#define NCTA    128
#define NTHR    256
#define KG_SZ   256
#define CG_COLS 64

// SMEM: padded bf16 tiles, row stride 264 elems (528B) -> conflict-free frag loads
#define ROW_STRIDE_B 528
#define TILE_BYTES   (64 * ROW_STRIDE_B)   // 33792
#define SM_BIAS 0
#define SM_A_HI 64
#define SM_A_LO (SM_A_HI + TILE_BYTES)
#define SM_W_HI (SM_A_LO + TILE_BYTES)
#define SM_W_LO (SM_W_HI + TILE_BYTES)
#define SM_TOTAL (SM_W_LO + TILE_BYTES)    // 135232

__device__ __align__(16) __nv_bfloat16 g_x_hi[T_STEPS * B_SZ * I_SZ];
__device__ __align__(16) __nv_bfloat16 g_x_lo[T_STEPS * B_SZ * I_SZ];
__device__ __align__(16) __nv_bfloat16 g_h_hi[B_SZ * H_SZ];
__device__ __align__(16) __nv_bfloat16 g_h_lo[B_SZ * H_SZ];
__device__ float    g_part[4 * G4 * B_SZ];   // [kg][col][b]
__device__ unsigned g_bar;

__device__ __forceinline__ void grid_barrier(unsigned target) {
    __syncthreads();
    if (threadIdx.x == 0) {
        unsigned* bar = &g_bar;
        asm volatile("red.release.gpu.add.u32 [%0], 1;" :: "l"(bar) : "memory");
        unsigned v;
        do {
            asm volatile("ld.acquire.gpu.u32 %0, [%1];" : "=r"(v) : "l"(bar) : "memory");
        } while (v < target);
    }
    __syncthreads();
}

__device__ __forceinline__ float sigmoidf_fast(float x) {
    return 1.0f / (1.0f + __expf(-x));
}

__device__ __forceinline__ void mma_bf16(float* d, const uint32_t* a, const uint32_t* b) {
    asm volatile(
        "mma.sync.aligned.m16n8k16.row.col.f32.bf16.bf16.f32 "
        "{%0,%1,%2,%3}, {%4,%5,%6,%7}, {%8,%9}, {%0,%1,%2,%3};"
        : "+f"(d[0]), "+f"(d[1]), "+f"(d[2]), "+f"(d[3])
        : "r"(a[0]), "r"(a[1]), "r"(a[2]), "r"(a[3]), "r"(b[0]), "r"(b[1]));
}

extern "C" __global__ void __launch_bounds__(NTHR, 1)
lstm_hmma_kernel(const float* __restrict__ x,
                 const float* __restrict__ hidden0,
                 const float* __restrict__ cell0,
                 const float* __restrict__ W,
                 const float* __restrict__ bias,
                 float* __restrict__ out)
{
    extern __shared__ char smem[];
    float* sbias = (float*)(smem + SM_BIAS);

    const int tid = threadIdx.x;
    const int bid = blockIdx.x;
    const int cg  = bid >> 2;
    const int kg  = bid & 3;
    const int wid = tid >> 5;
    const int lid = tid & 31;
    const int grp = lid >> 2;     // groupID 0..7
    const int tg  = lid & 3;      // thread-in-group

    // warp tile: 4 warps along M (batch), 2 along N (cols)
    const int m_base = (wid >> 1) * 16;
    const int n_base = (wid & 1) * 32;

    // elementwise ownership
    const int eb  = tid >> 2;
    const int ejj = tid & 3;
    const int ej  = bid * 4 + ejj;

    // ---- init: W slice -> SMEM bf16 hi/lo, layout [n][k] padded ----
    {
        const float* wsrc = W + (size_t)(kg * KG_SZ) * G4 + cg * CG_COLS;
        for (int idx = tid; idx < KG_SZ * CG_COLS; idx += NTHR) {
            int n = idx & 63;          // coalesced along n
            int k = idx >> 6;
            float w = wsrc[(size_t)k * G4 + n];
            __nv_bfloat16 hi = __float2bfloat16_rn(w);
            __nv_bfloat16 lo = __float2bfloat16_rn(w - __bfloat162float(hi));
            int o = n * ROW_STRIDE_B + k * 2;
            *(__nv_bfloat16*)(smem + SM_W_HI + o) = hi;
            *(__nv_bfloat16*)(smem + SM_W_LO + o) = lo;
        }
    }
    if (tid < 16) {
        int gate = tid >> 2;
        int jj   = tid & 3;
        sbias[tid] = bias[gate * H_SZ + bid * 4 + jj];
    }
    // ---- pre-split x -> bf16 hi/lo (grid-strided) ----
    {
        const float4* x4 = (const float4*)x;
        const int n4 = T_STEPS * B_SZ * I_SZ / 4;
        for (int i = bid * NTHR + tid; i < n4; i += NCTA * NTHR) {
            float4 v = x4[i];
            __nv_bfloat16 h0 = __float2bfloat16_rn(v.x);
            __nv_bfloat16 h1 = __float2bfloat16_rn(v.y);
            __nv_bfloat16 h2 = __float2bfloat16_rn(v.z);
            __nv_bfloat16 h3 = __float2bfloat16_rn(v.w);
            __nv_bfloat162* dh = (__nv_bfloat162*)(g_x_hi + 4 * (size_t)i);
            dh[0] = __nv_bfloat162(h0, h1);
            dh[1] = __nv_bfloat162(h2, h3);
            __nv_bfloat162* dl = (__nv_bfloat162*)(g_x_lo + 4 * (size_t)i);
            dl[0] = __nv_bfloat162(__float2bfloat16_rn(v.x - __bfloat162float(h0)),
                                   __float2bfloat16_rn(v.y - __bfloat162float(h1)));
            dl[1] = __nv_bfloat162(__float2bfloat16_rn(v.z - __bfloat162float(h2)),
                                   __float2bfloat16_rn(v.w - __bfloat162float(h3)));
        }
    }
    // ---- state init ----
    float c_state = cell0[eb * H_SZ + ej];
    {
        float hv = hidden0[eb * H_SZ + ej];
        __nv_bfloat16 hh = __float2bfloat16_rn(hv);
        g_h_hi[eb * H_SZ + ej] = hh;
        g_h_lo[eb * H_SZ + ej] = __float2bfloat16_rn(hv - __bfloat162float(hh));
    }
    float h_last = 0.0f;

    unsigned bar_n = 1;
    grid_barrier(NCTA * bar_n); bar_n++;

    // ---- time loop ----
    for (int t = 0; t < T_STEPS; t++) {
        // stage A hi/lo: rows b=0..63, k slice [kg*256, +256), padded smem
        {
            const __nv_bfloat16* sh;
            const __nv_bfloat16* sl;
            if (kg < 2) {
                size_t off = (size_t)t * B_SZ * I_SZ + kg * KG_SZ;
                sh = g_x_hi + off;
                sl = g_x_lo + off;
            } else {
                sh = g_h_hi + (kg - 2) * KG_SZ;
                sl = g_h_lo + (kg - 2) * KG_SZ;
            }
            #pragma unroll
            for (int it = 0; it < 8; it++) {
                int idx = tid + it * NTHR;       // 0..2047
                int r   = idx >> 5;              // 0..63
                int c16 = idx & 31;              // 16B unit
                uint4 vh = *(const uint4*)(sh + (size_t)r * 512 + c16 * 8);
                uint4 vl = *(const uint4*)(sl + (size_t)r * 512 + c16 * 8);
                int o = r * ROW_STRIDE_B + c16 * 16;
                *(uint4*)(smem + SM_A_HI + o) = vh;
                *(uint4*)(smem + SM_A_LO + o) = vl;
            }
        }
        __syncthreads();

        // ---- 64x64x256 GEMM: 3-pass bf16 split, m16n8k16 ----
        float acc[4][4];
        #pragma unroll
        for (int i = 0; i < 4; i++) {
            acc[i][0] = 0.f; acc[i][1] = 0.f; acc[i][2] = 0.f; acc[i][3] = 0.f;
        }
        {
            const char* arow = smem + (m_base + grp) * ROW_STRIDE_B + tg * 4;
            #pragma unroll 4
            for (int ks = 0; ks < 16; ks++) {
                const int kb = ks * 32;   // byte offset of k0 within row
                uint32_t a_hi[4], a_lo[4];
                a_hi[0] = *(const uint32_t*)(arow + SM_A_HI + kb);
                a_hi[1] = *(const uint32_t*)(arow + SM_A_HI + 8 * ROW_STRIDE_B + kb);
                a_hi[2] = *(const uint32_t*)(arow + SM_A_HI + kb + 16);
                a_hi[3] = *(const uint32_t*)(arow + SM_A_HI + 8 * ROW_STRIDE_B + kb + 16);
                a_lo[0] = *(const uint32_t*)(arow + SM_A_LO + kb);
                a_lo[1] = *(const uint32_t*)(arow + SM_A_LO + 8 * ROW_STRIDE_B + kb);
                a_lo[2] = *(const uint32_t*)(arow + SM_A_LO + kb + 16);
                a_lo[3] = *(const uint32_t*)(arow + SM_A_LO + 8 * ROW_STRIDE_B + kb + 16);
                #pragma unroll
                for (int nt = 0; nt < 4; nt++) {
                    const char* brow = smem + (n_base + nt * 8 + grp) * ROW_STRIDE_B + tg * 4 + kb;
                    uint32_t b_hi[2], b_lo[2];
                    b_hi[0] = *(const uint32_t*)(brow + SM_W_HI);
                    b_hi[1] = *(const uint32_t*)(brow + SM_W_HI + 16);
                    b_lo[0] = *(const uint32_t*)(brow + SM_W_LO);
                    b_lo[1] = *(const uint32_t*)(brow + SM_W_LO + 16);
                    mma_bf16(acc[nt], a_hi, b_hi);
                    mma_bf16(acc[nt], a_hi, b_lo);
                    mma_bf16(acc[nt], a_lo, b_hi);
                }
            }
        }
        // write partials: g_part[kg][col][b]
        {
            #pragma unroll
            for (int nt = 0; nt < 4; nt++) {
                int col = cg * CG_COLS + n_base + nt * 8 + tg * 2;
                int b0  = m_base + grp;
                g_part[((size_t)kg * G4 + col)     * B_SZ + b0]     = acc[nt][0];
                g_part[((size_t)kg * G4 + col + 1) * B_SZ + b0]     = acc[nt][1];
                g_part[((size_t)kg * G4 + col)     * B_SZ + b0 + 8] = acc[nt][2];
                g_part[((size_t)kg * G4 + col + 1) * B_SZ + b0 + 8] = acc[nt][3];
            }
        }

        grid_barrier(NCTA * bar_n); bar_n++;

        // elementwise: reduce 4 partials + bias, LSTM cell, emit h (fp32 + bf16 hi/lo)
        {
            float g0 = sbias[0 * 4 + ejj];
            float g1 = sbias[1 * 4 + ejj];
            float g2 = sbias[2 * 4 + ejj];
            float g3 = sbias[3 * 4 + ejj];
            #pragma unroll
            for (int kk = 0; kk < 4; kk++) {
                g0 += g_part[((size_t)kk * G4 + 0 * H_SZ + ej) * B_SZ + eb];
                g1 += g_part[((size_t)kk * G4 + 1 * H_SZ + ej) * B_SZ + eb];
                g2 += g_part[((size_t)kk * G4 + 2 * H_SZ + ej) * B_SZ + eb];
                g3 += g_part[((size_t)kk * G4 + 3 * H_SZ + ej) * B_SZ + eb];
            }
            float f  = sigmoidf_fast(g0);
            float ii = sigmoidf_fast(g1);
            float cd = tanhf(g2);
            float o  = sigmoidf_fast(g3);
            c_state = f * c_state + ii * cd;
            float h = o * tanhf(c_state);
            h_last = h;
            out[(size_t)t * (B_SZ * H_SZ) + eb * H_SZ + ej] = h;
            __nv_bfloat16 hh = __float2bfloat16_rn(h);
            g_h_hi[eb * H_SZ + ej] = hh;
            g_h_lo[eb * H_SZ + ej] = __float2bfloat16_rn(h - __bfloat162float(hh));
        }

        grid_barrier(NCTA * bar_n); bar_n++;
    }

    // final states
    {
        size_t base = (size_t)T_STEPS * B_SZ * H_SZ;
        out[base + eb * H_SZ + ej] = h_last;
        out[base + B_SZ * H_SZ + eb * H_SZ + ej] = c_state;
    }
}

extern "C" void kernel_launch(void* const* d_in, const int* in_sizes, int n_in,
                              void* d_out, int out_size)
{
    (void)in_sizes; (void)n_in; (void)out_size;
    const float* x       = (const float*)d_in[0];
    const float* hidden0 = (const float*)d_in[1];
    const float* cell0   = (const float*)d_in[2];
    const float* W       = (const float*)d_in[3];
    const float* bias    = (const float*)d_in[4];
    float* out = (float*)d_out;

    void* bar_addr = nullptr;
    cudaGetSymbolAddress(&bar_addr, g_bar);
    cudaMemsetAsync(bar_addr, 0, sizeof(unsigned));

    cudaFuncSetAttribute(lstm_hmma_kernel,
                         cudaFuncAttributeMaxDynamicSharedMemorySize, SM_TOTAL);

    lstm_hmma_kernel<<<NCTA, NTHR, SM_TOTAL>>>(x, hidden0, cell0, W, bias, out);
}